// round 4
// baseline (speedup 1.0000x reference)
#include <cuda_runtime.h>
#include <cuda_fp16.h>
#include <cstdint>

// Problem shape (fixed by the reference)
#define NB 32
#define NS 4096
#define NH 512
#define NROWS (NB * NS)   // 131072 rows of the fused [B*S, H] GEMM

// ---------------------------------------------------------------------------
// Device scratch (no cudaMalloc allowed)
// ---------------------------------------------------------------------------
__device__ float g_qt[NB * NH];                       // q@Wq + bq + bv, fp32
__device__ __align__(16) __half g_Wt[NH * NH];        // Wv^T fp16: Wt[n][k] = Wv[k][n]
__device__ float g_scores[NB * NS];                   // pre-softmax scores
__device__ float g_partial[NB * 8 * NH];              // split-K context partials

// ---------------------------------------------------------------------------
// Helpers
// ---------------------------------------------------------------------------
__device__ __forceinline__ float tanh_fast(float x) {
    float y;
    asm("tanh.approx.f32 %0, %1;" : "=f"(y) : "f"(x));
    return y;
}

// m16n8k16 fp16 MMA, fp32 accumulate (sm_80+, valid on plain sm_100 target)
__device__ __forceinline__ void mma16816(float* d,
                                         uint32_t a0, uint32_t a1,
                                         uint32_t a2, uint32_t a3,
                                         uint32_t b0, uint32_t b1) {
    asm volatile(
        "mma.sync.aligned.m16n8k16.row.col.f32.f16.f16.f32 "
        "{%0,%1,%2,%3}, {%4,%5,%6,%7}, {%8,%9}, {%0,%1,%2,%3};"
        : "+f"(d[0]), "+f"(d[1]), "+f"(d[2]), "+f"(d[3])
        : "r"(a0), "r"(a1), "r"(a2), "r"(a3), "r"(b0), "r"(b1));
}

// ---------------------------------------------------------------------------
// Kernel 1: q_t[b][k] = bq[k] + bv[k] + sum_h query[b][h] * Wq[h][k]
// (bv folded in; bc dropped: constant per-row shift is softmax-invariant and
//  scores themselves are not part of the output.)
// ---------------------------------------------------------------------------
__global__ void prep_qt_kernel(const float* __restrict__ query,
                               const float* __restrict__ Wq,
                               const float* __restrict__ bq,
                               const float* __restrict__ bv) {
    __shared__ float qs[NH];
    int b = blockIdx.x;
    int k = threadIdx.x;
    qs[k] = query[b * NH + k];
    __syncthreads();
    float acc = bq[k] + bv[k];
#pragma unroll 8
    for (int h = 0; h < NH; h++)
        acc = fmaf(qs[h], Wq[h * NH + k], acc);
    g_qt[b * NH + k] = acc;
}

// ---------------------------------------------------------------------------
// Kernel 2: Wt[n][k] = fp16(Wv[k][n])  (B operand: D[m][n] = sum_k A[m,k]*B[n,k])
// ---------------------------------------------------------------------------
__global__ void prep_wt_kernel(const float* __restrict__ Wv) {
    int i = blockIdx.x * blockDim.x + threadIdx.x;  // 262144 total
    int n = i >> 9;
    int h = i & 511;
    g_Wt[i] = __float2half_rn(Wv[h * NH + n]);
}

// ---------------------------------------------------------------------------
// Kernel 3: fused scores via HMMA mma.sync, DOUBLE-BUFFERED A staging.
// CTA: 512 threads (16 warps), M = 64 rows, N = 512 (full H), K = 512.
// Warp w owns output cols [32w, 32w+32): acc = 4 mtiles x 4 ntiles x 4 = 64 fp32.
// K in 4 chunks of 128. Chunk kc+1's global loads (values fp32) are issued into
// registers BEFORE chunk kc's 512 MMAs (latency hidden behind tensor work),
// then converted fp16 and stored into the alternate smem buffer; ONE
// __syncthreads per chunk. A smem rows padded to 136 halves -> fragment LDS
// bank = 4g+t, conflict-free. B fragments read straight from g_Wt in L2.
// Epilogue: score[row] = sum_h wc[h]*tanh(qt[b][h] + v_t[row][h]) — the
// 256 MB v_t never touches memory.
// ---------------------------------------------------------------------------
#define AS_STRIDE 136   // halves per A smem row (136*2 = 272 B -> bank shift 4/row)

__global__ void __launch_bounds__(512) scores_kernel(const float* __restrict__ values,
                                                     const float* __restrict__ wc) {
    __shared__ __half As[2][64 * AS_STRIDE];   // 2 x 17408 B
    __shared__ float qt_s[NH];
    __shared__ float wc_s[NH];
    __shared__ float red[64 * 16];

    int tid = threadIdx.x;
    int w = tid >> 5;
    int l = tid & 31;
    int g = l >> 2;   // group id (0..7)
    int t = l & 3;    // thread-in-group
    int row_base = blockIdx.x * 64;
    int b = row_base >> 12;  // 4096 rows per batch, 64 | 4096

    for (int i = tid; i < NH; i += 512) {
        qt_s[i] = g_qt[b * NH + i];
        wc_s[i] = wc[i];
    }

    float acc[4][4][4];
#pragma unroll
    for (int mt = 0; mt < 4; mt++)
#pragma unroll
        for (int nt = 0; nt < 4; nt++)
#pragma unroll
            for (int j = 0; j < 4; j++)
                acc[mt][nt][j] = 0.f;

    int n0 = w * 32;
    const __half* bp[4];
#pragma unroll
    for (int nt = 0; nt < 4; nt++)
        bp[nt] = g_Wt + (n0 + nt * 8 + g) * NH + t * 2;

    // This thread stages 4 rows (r = i*16 + w), one float4 (=8 halves) per row.
    int arow_r[1];
    (void)arow_r;
    float4 pf[4];

    // ---- preload chunk 0 and stage into As[0] ----
#pragma unroll
    for (int i = 0; i < 4; i++) {
        int r = i * 16 + w;
        pf[i] = *((const float4*)(values + (size_t)(row_base + r) * NH) + l);
    }
#pragma unroll
    for (int i = 0; i < 4; i++) {
        int r = i * 16 + w;
        __half2 h0 = __floats2half2_rn(pf[i].x, pf[i].y);
        __half2 h1 = __floats2half2_rn(pf[i].z, pf[i].w);
        uint2 st;
        st.x = *(uint32_t*)&h0;
        st.y = *(uint32_t*)&h1;
        *(uint2*)(&As[0][r * AS_STRIDE + l * 4]) = st;
    }
    __syncthreads();

    for (int kc = 0; kc < 4; kc++) {
        int cur = kc & 1;

        // ---- issue next chunk's LDGs (results consumed only after the MMAs) ----
        if (kc < 3) {
#pragma unroll
            for (int i = 0; i < 4; i++) {
                int r = i * 16 + w;
                pf[i] = *((const float4*)(values + (size_t)(row_base + r) * NH +
                                          (kc + 1) * 128) + l);
            }
        }

        // ---- 8 k-steps of K=16 on As[cur] ----
#pragma unroll
        for (int ks = 0; ks < 8; ks++) {
            int kg = kc * 128 + ks * 16;
            uint32_t bf[4][2];
#pragma unroll
            for (int nt = 0; nt < 4; nt++) {
                bf[nt][0] = *(const uint32_t*)(bp[nt] + kg);
                bf[nt][1] = *(const uint32_t*)(bp[nt] + kg + 8);
            }
#pragma unroll
            for (int mt = 0; mt < 4; mt++) {
                const __half* ab = &As[cur][(mt * 16 + g) * AS_STRIDE + ks * 16 + t * 2];
                uint32_t a0 = *(const uint32_t*)ab;
                uint32_t a1 = *(const uint32_t*)(ab + 8 * AS_STRIDE);
                uint32_t a2 = *(const uint32_t*)(ab + 8);
                uint32_t a3 = *(const uint32_t*)(ab + 8 * AS_STRIDE + 8);
#pragma unroll
                for (int nt = 0; nt < 4; nt++)
                    mma16816(acc[mt][nt], a0, a1, a2, a3, bf[nt][0], bf[nt][1]);
            }
        }

        // ---- convert + store prefetched chunk into the other buffer ----
        if (kc < 3) {
#pragma unroll
            for (int i = 0; i < 4; i++) {
                int r = i * 16 + w;
                __half2 h0 = __floats2half2_rn(pf[i].x, pf[i].y);
                __half2 h1 = __floats2half2_rn(pf[i].z, pf[i].w);
                uint2 st;
                st.x = *(uint32_t*)&h0;
                st.y = *(uint32_t*)&h1;
                *(uint2*)(&As[cur ^ 1][r * AS_STRIDE + l * 4]) = st;
            }
        }
        __syncthreads();
    }

    // ---- epilogue: wc * tanh(qt + v_t), reduce over this warp's 32 cols ----
    float rs[8];
#pragma unroll
    for (int i = 0; i < 8; i++) rs[i] = 0.f;

#pragma unroll
    for (int nt = 0; nt < 4; nt++) {
        int c0 = n0 + nt * 8 + t * 2;
        float w0 = wc_s[c0], w1 = wc_s[c0 + 1];
        float q0 = qt_s[c0], q1 = qt_s[c0 + 1];
#pragma unroll
        for (int mt = 0; mt < 4; mt++) {
            float* d = acc[mt][nt];
            rs[mt * 2]     += w0 * tanh_fast(d[0] + q0) + w1 * tanh_fast(d[1] + q1);
            rs[mt * 2 + 1] += w0 * tanh_fast(d[2] + q0) + w1 * tanh_fast(d[3] + q1);
        }
    }
#pragma unroll
    for (int i = 0; i < 8; i++) {
        rs[i] += __shfl_xor_sync(0xffffffffu, rs[i], 1);
        rs[i] += __shfl_xor_sync(0xffffffffu, rs[i], 2);
    }
    if (t == 0) {
#pragma unroll
        for (int mt = 0; mt < 4; mt++) {
            red[(mt * 16 + g) * 16 + w]     = rs[mt * 2];
            red[(mt * 16 + g + 8) * 16 + w] = rs[mt * 2 + 1];
        }
    }
    __syncthreads();
    if (tid < 64) {
        float s = 0.f;
#pragma unroll
        for (int j = 0; j < 16; j++) s += red[tid * 16 + j];
        g_scores[row_base + tid] = s;
    }
}

// ---------------------------------------------------------------------------
// Kernel 4: softmax over S per batch, writes attn into d_out[B*H ..]
// ---------------------------------------------------------------------------
__global__ void softmax_kernel(const int* __restrict__ mask, float* __restrict__ out) {
    __shared__ float red[1024];
    int b = blockIdx.x;
    int tid = threadIdx.x;  // 1024 threads, 4 elems each

    float v[4];
#pragma unroll
    for (int i = 0; i < 4; i++) {
        int s = tid + i * 1024;
        float sc = g_scores[b * NS + s];
        v[i] = (mask[b * NS + s] == 0) ? -1e30f : sc;
    }
    float mx = fmaxf(fmaxf(v[0], v[1]), fmaxf(v[2], v[3]));
    red[tid] = mx;
    __syncthreads();
    for (int off = 512; off > 0; off >>= 1) {
        if (tid < off) red[tid] = fmaxf(red[tid], red[tid + off]);
        __syncthreads();
    }
    mx = red[0];
    __syncthreads();

    float e[4];
    float sm = 0.f;
#pragma unroll
    for (int i = 0; i < 4; i++) {
        e[i] = __expf(v[i] - mx);
        sm += e[i];
    }
    red[tid] = sm;
    __syncthreads();
    for (int off = 512; off > 0; off >>= 1) {
        if (tid < off) red[tid] += red[tid + off];
        __syncthreads();
    }
    float inv = 1.f / red[0];

    float* attn = out + NB * NH;
#pragma unroll
    for (int i = 0; i < 4; i++)
        attn[b * NS + tid + i * 1024] = e[i] * inv;
}

// ---------------------------------------------------------------------------
// Kernel 5: split-K context partials: block (b, sp) sums 512 s-rows for all H
// ---------------------------------------------------------------------------
__global__ void context_partial_kernel(const float* __restrict__ values,
                                       const float* __restrict__ out) {
    int bs = blockIdx.x;             // 0..255
    int b = bs >> 3;
    int sp = bs & 7;
    int h = threadIdx.x;             // 512
    const float* attn = out + NB * NH + b * NS + sp * 512;
    const float* vb = values + ((size_t)b * NS + (size_t)sp * 512) * NH;
    float acc = 0.f;
#pragma unroll 8
    for (int s = 0; s < 512; s++)
        acc = fmaf(attn[s], vb[(size_t)s * NH + h], acc);
    g_partial[bs * NH + h] = acc;
}

// ---------------------------------------------------------------------------
// Kernel 6: reduce partials -> context in d_out[0 .. B*H)
// ---------------------------------------------------------------------------
__global__ void context_reduce_kernel(float* __restrict__ out) {
    int b = blockIdx.x;
    int h = threadIdx.x;
    float acc = 0.f;
#pragma unroll
    for (int p = 0; p < 8; p++)
        acc += g_partial[(b * 8 + p) * NH + h];
    out[b * NH + h] = acc;
}

// ---------------------------------------------------------------------------
// Launch: out = [ context (B*H) | attn (B*S) ]  (tuple order of reference)
// ---------------------------------------------------------------------------
extern "C" void kernel_launch(void* const* d_in, const int* in_sizes, int n_in,
                              void* d_out, int out_size) {
    const float* query  = (const float*)d_in[0];
    const float* values = (const float*)d_in[1];
    const int*   mask   = (const int*)  d_in[2];
    const float* Wq     = (const float*)d_in[3];
    const float* bq     = (const float*)d_in[4];
    const float* Wv     = (const float*)d_in[5];
    const float* bv     = (const float*)d_in[6];
    const float* wc     = (const float*)d_in[7];
    // d_in[8] = bc: softmax-invariant, unused.
    float* out = (float*)d_out;

    prep_qt_kernel<<<NB, NH>>>(query, Wq, bq, bv);
    prep_wt_kernel<<<512, 512>>>(Wv);
    scores_kernel<<<NROWS / 64, 512>>>(values, wc);
    softmax_kernel<<<NB, 1024>>>(mask, out);
    context_partial_kernel<<<NB * 8, 512>>>(values, out);
    context_reduce_kernel<<<NB, 512>>>(out);
}

// round 6
// speedup vs baseline: 1.5922x; 1.5922x over previous
#include <cuda_runtime.h>
#include <cuda_fp16.h>
#include <cstdint>

// Problem shape (fixed by the reference)
#define NB 32
#define NS 4096
#define NH 512
#define NROWS (NB * NS)   // 131072 rows of the fused [B*S, H] GEMM

// ---------------------------------------------------------------------------
// Device scratch (no cudaMalloc allowed)
// ---------------------------------------------------------------------------
__device__ float g_qt[NB * NH];                   // q@Wq + bq + bv, fp32
// B operand in FRAGMENT order: [nb(64)][kstep(32)][lane(32)] = {b0,b1} uint2.
// b0 = fp16(Wv[k0][n]),fp16(Wv[k0+1][n]); b1 = same at k0+8, with
// n = nb*8 + (lane>>2), k0 = kstep*16 + (lane&3)*2.  Warp fragment load is a
// single fully-coalesced 256B LDG.64 burst (lane l reads 8B at base+8l).
__device__ __align__(16) uint2 g_Wfrag[64 * 32 * 32];
__device__ float g_scores[NB * NS];               // pre-softmax scores
__device__ float g_partial[NB * 8 * NH];          // split-K context partials

// ---------------------------------------------------------------------------
// Helpers
// ---------------------------------------------------------------------------
__device__ __forceinline__ float tanh_fast(float x) {
    float y;
    asm("tanh.approx.f32 %0, %1;" : "=f"(y) : "f"(x));
    return y;
}

// m16n8k16 fp16 MMA, fp32 accumulate (sm_80+, valid on plain sm_100 target)
__device__ __forceinline__ void mma16816(float* d,
                                         uint32_t a0, uint32_t a1,
                                         uint32_t a2, uint32_t a3,
                                         uint32_t b0, uint32_t b1) {
    asm volatile(
        "mma.sync.aligned.m16n8k16.row.col.f32.f16.f16.f32 "
        "{%0,%1,%2,%3}, {%4,%5,%6,%7}, {%8,%9}, {%0,%1,%2,%3};"
        : "+f"(d[0]), "+f"(d[1]), "+f"(d[2]), "+f"(d[3])
        : "r"(a0), "r"(a1), "r"(a2), "r"(a3), "r"(b0), "r"(b1));
}

// ---------------------------------------------------------------------------
// Kernel 1: q_t[b][k] = bq[k] + bv[k] + sum_h query[b][h] * Wq[h][k]
// (bv folded in; bc dropped: constant per-row shift is softmax-invariant and
//  scores themselves are not part of the output.)
// ---------------------------------------------------------------------------
__global__ void prep_qt_kernel(const float* __restrict__ query,
                               const float* __restrict__ Wq,
                               const float* __restrict__ bq,
                               const float* __restrict__ bv) {
    __shared__ float qs[NH];
    int b = blockIdx.x;
    int k = threadIdx.x;
    qs[k] = query[b * NH + k];
    __syncthreads();
    float acc = bq[k] + bv[k];
#pragma unroll 8
    for (int h = 0; h < NH; h++)
        acc = fmaf(qs[h], Wq[h * NH + k], acc);
    g_qt[b * NH + k] = acc;
}

// ---------------------------------------------------------------------------
// Kernel 2: pack Wv -> fragment-ordered fp16 B operand g_Wfrag (512 KB).
// One thread per uint2.  Wv is 1 MB -> L2-resident; cost ~5 us.
// ---------------------------------------------------------------------------
__global__ void prep_wfrag_kernel(const float* __restrict__ Wv) {
    int i = blockIdx.x * blockDim.x + threadIdx.x;   // 65536 total
    int lane = i & 31;
    int ks = (i >> 5) & 31;
    int nb = i >> 10;
    int g = lane >> 2;
    int t = lane & 3;
    int n = nb * 8 + g;
    int k0 = ks * 16 + t * 2;

    __half2 b0 = __floats2half2_rn(Wv[(size_t)k0 * NH + n],
                                   Wv[(size_t)(k0 + 1) * NH + n]);
    __half2 b1 = __floats2half2_rn(Wv[(size_t)(k0 + 8) * NH + n],
                                   Wv[(size_t)(k0 + 9) * NH + n]);
    uint2 u;
    u.x = *(uint32_t*)&b0;
    u.y = *(uint32_t*)&b1;
    g_Wfrag[i] = u;
}

// ---------------------------------------------------------------------------
// Kernel 3: fused scores via HMMA mma.sync, double-buffered A staging +
// fragment-ordered B.
// CTA: 512 threads (16 warps), M = 64 rows, N = 512 (full H), K = 512.
// Warp w owns output cols [32w, 32w+32): acc = 4 mtiles x 4 ntiles x 4 = 64 fp32.
// K in 4 chunks of 128: next chunk's A LDGs issue before current chunk's 512
// MMAs; fp32->fp16 conversion + smem store after; one __syncthreads per chunk.
// A smem rows padded to 136 halves -> fragment LDS bank = 4g+t, conflict-free.
// B fragments: one coalesced LDG.64 per (nt,ks) from g_Wfrag in L2.
// Epilogue: score[row] = sum_h wc[h]*tanh(qt[b][h] + v_t[row][h]) — the
// 256 MB v_t never touches memory.
// ---------------------------------------------------------------------------
#define AS_STRIDE 136   // halves per A smem row (136*2 = 272 B -> bank shift 4/row)

__global__ void __launch_bounds__(512) scores_kernel(const float* __restrict__ values,
                                                     const float* __restrict__ wc) {
    __shared__ __half As[2][64 * AS_STRIDE];   // 2 x 17408 B
    __shared__ float qt_s[NH];
    __shared__ float wc_s[NH];
    __shared__ float red[64 * 16];

    int tid = threadIdx.x;
    int w = tid >> 5;
    int l = tid & 31;
    int g = l >> 2;   // group id (0..7)
    int t = l & 3;    // thread-in-group
    int row_base = blockIdx.x * 64;
    int b = row_base >> 12;  // 4096 rows per batch, 64 | 4096

    for (int i = tid; i < NH; i += 512) {
        qt_s[i] = g_qt[b * NH + i];
        wc_s[i] = wc[i];
    }

    float acc[4][4][4];
#pragma unroll
    for (int mt = 0; mt < 4; mt++)
#pragma unroll
        for (int nt = 0; nt < 4; nt++)
#pragma unroll
            for (int j = 0; j < 4; j++)
                acc[mt][nt][j] = 0.f;

    // Fragment base for this warp+lane: nb = w*4 + nt, kstep = kc*8 + ks.
    const uint2* wf = g_Wfrag + ((size_t)(w * 4) * 32) * 32 + l;

    float4 pf[4];

    // ---- preload chunk 0 and stage into As[0] ----
#pragma unroll
    for (int i = 0; i < 4; i++) {
        int r = i * 16 + w;
        pf[i] = *((const float4*)(values + (size_t)(row_base + r) * NH) + l);
    }
#pragma unroll
    for (int i = 0; i < 4; i++) {
        int r = i * 16 + w;
        __half2 h0 = __floats2half2_rn(pf[i].x, pf[i].y);
        __half2 h1 = __floats2half2_rn(pf[i].z, pf[i].w);
        uint2 st;
        st.x = *(uint32_t*)&h0;
        st.y = *(uint32_t*)&h1;
        *(uint2*)(&As[0][r * AS_STRIDE + l * 4]) = st;
    }
    __syncthreads();

    for (int kc = 0; kc < 4; kc++) {
        int cur = kc & 1;

        // ---- issue next chunk's LDGs (results consumed only after the MMAs) ----
        if (kc < 3) {
#pragma unroll
            for (int i = 0; i < 4; i++) {
                int r = i * 16 + w;
                pf[i] = *((const float4*)(values + (size_t)(row_base + r) * NH +
                                          (kc + 1) * 128) + l);
            }
        }

        // ---- 8 k-steps of K=16 on As[cur] ----
#pragma unroll
        for (int ks = 0; ks < 8; ks++) {
            int kstep = kc * 8 + ks;
            uint2 bf[4];
#pragma unroll
            for (int nt = 0; nt < 4; nt++)
                bf[nt] = wf[((size_t)nt * 32 + kstep) * 32];   // coalesced LDG.64
#pragma unroll
            for (int mt = 0; mt < 4; mt++) {
                const __half* ab = &As[cur][(mt * 16 + g) * AS_STRIDE + ks * 16 + t * 2];
                uint32_t a0 = *(const uint32_t*)ab;
                uint32_t a1 = *(const uint32_t*)(ab + 8 * AS_STRIDE);
                uint32_t a2 = *(const uint32_t*)(ab + 8);
                uint32_t a3 = *(const uint32_t*)(ab + 8 * AS_STRIDE + 8);
#pragma unroll
                for (int nt = 0; nt < 4; nt++)
                    mma16816(acc[mt][nt], a0, a1, a2, a3, bf[nt].x, bf[nt].y);
            }
        }

        // ---- convert + store prefetched chunk into the other buffer ----
        if (kc < 3) {
#pragma unroll
            for (int i = 0; i < 4; i++) {
                int r = i * 16 + w;
                __half2 h0 = __floats2half2_rn(pf[i].x, pf[i].y);
                __half2 h1 = __floats2half2_rn(pf[i].z, pf[i].w);
                uint2 st;
                st.x = *(uint32_t*)&h0;
                st.y = *(uint32_t*)&h1;
                *(uint2*)(&As[cur ^ 1][r * AS_STRIDE + l * 4]) = st;
            }
        }
        __syncthreads();
    }

    // ---- epilogue: wc * tanh(qt + v_t), reduce over this warp's 32 cols ----
    float rs[8];
#pragma unroll
    for (int i = 0; i < 8; i++) rs[i] = 0.f;

#pragma unroll
    for (int nt = 0; nt < 4; nt++) {
        int c0 = w * 32 + nt * 8 + t * 2;
        float w0 = wc_s[c0], w1 = wc_s[c0 + 1];
        float q0 = qt_s[c0], q1 = qt_s[c0 + 1];
#pragma unroll
        for (int mt = 0; mt < 4; mt++) {
            float* d = acc[mt][nt];
            rs[mt * 2]     += w0 * tanh_fast(d[0] + q0) + w1 * tanh_fast(d[1] + q1);
            rs[mt * 2 + 1] += w0 * tanh_fast(d[2] + q0) + w1 * tanh_fast(d[3] + q1);
        }
    }
#pragma unroll
    for (int i = 0; i < 8; i++) {
        rs[i] += __shfl_xor_sync(0xffffffffu, rs[i], 1);
        rs[i] += __shfl_xor_sync(0xffffffffu, rs[i], 2);
    }
    if (t == 0) {
#pragma unroll
        for (int mt = 0; mt < 4; mt++) {
            red[(mt * 16 + g) * 16 + w]     = rs[mt * 2];
            red[(mt * 16 + g + 8) * 16 + w] = rs[mt * 2 + 1];
        }
    }
    __syncthreads();
    if (tid < 64) {
        float s = 0.f;
#pragma unroll
        for (int j = 0; j < 16; j++) s += red[tid * 16 + j];
        g_scores[row_base + tid] = s;
    }
}

// ---------------------------------------------------------------------------
// Kernel 4: softmax over S per batch, writes attn into d_out[B*H ..]
// ---------------------------------------------------------------------------
__global__ void softmax_kernel(const int* __restrict__ mask, float* __restrict__ out) {
    __shared__ float red[1024];
    int b = blockIdx.x;
    int tid = threadIdx.x;  // 1024 threads, 4 elems each

    float v[4];
#pragma unroll
    for (int i = 0; i < 4; i++) {
        int s = tid + i * 1024;
        float sc = g_scores[b * NS + s];
        v[i] = (mask[b * NS + s] == 0) ? -1e30f : sc;
    }
    float mx = fmaxf(fmaxf(v[0], v[1]), fmaxf(v[2], v[3]));
    red[tid] = mx;
    __syncthreads();
    for (int off = 512; off > 0; off >>= 1) {
        if (tid < off) red[tid] = fmaxf(red[tid], red[tid + off]);
        __syncthreads();
    }
    mx = red[0];
    __syncthreads();

    float e[4];
    float sm = 0.f;
#pragma unroll
    for (int i = 0; i < 4; i++) {
        e[i] = __expf(v[i] - mx);
        sm += e[i];
    }
    red[tid] = sm;
    __syncthreads();
    for (int off = 512; off > 0; off >>= 1) {
        if (tid < off) red[tid] += red[tid + off];
        __syncthreads();
    }
    float inv = 1.f / red[0];

    float* attn = out + NB * NH;
#pragma unroll
    for (int i = 0; i < 4; i++)
        attn[b * NS + tid + i * 1024] = e[i] * inv;
}

// ---------------------------------------------------------------------------
// Kernel 5: split-K context partials: block (b, sp) sums 512 s-rows for all H
// ---------------------------------------------------------------------------
__global__ void context_partial_kernel(const float* __restrict__ values,
                                       const float* __restrict__ out) {
    int bs = blockIdx.x;             // 0..255
    int b = bs >> 3;
    int sp = bs & 7;
    int h = threadIdx.x;             // 512
    const float* attn = out + NB * NH + b * NS + sp * 512;
    const float* vb = values + ((size_t)b * NS + (size_t)sp * 512) * NH;
    float acc = 0.f;
#pragma unroll 8
    for (int s = 0; s < 512; s++)
        acc = fmaf(attn[s], vb[(size_t)s * NH + h], acc);
    g_partial[bs * NH + h] = acc;
}

// ---------------------------------------------------------------------------
// Kernel 6: reduce partials -> context in d_out[0 .. B*H)
// ---------------------------------------------------------------------------
__global__ void context_reduce_kernel(float* __restrict__ out) {
    int b = blockIdx.x;
    int h = threadIdx.x;
    float acc = 0.f;
#pragma unroll
    for (int p = 0; p < 8; p++)
        acc += g_partial[(b * 8 + p) * NH + h];
    out[b * NH + h] = acc;
}

// ---------------------------------------------------------------------------
// Launch: out = [ context (B*H) | attn (B*S) ]  (tuple order of reference)
// ---------------------------------------------------------------------------
extern "C" void kernel_launch(void* const* d_in, const int* in_sizes, int n_in,
                              void* d_out, int out_size) {
    const float* query  = (const float*)d_in[0];
    const float* values = (const float*)d_in[1];
    const int*   mask   = (const int*)  d_in[2];
    const float* Wq     = (const float*)d_in[3];
    const float* bq     = (const float*)d_in[4];
    const float* Wv     = (const float*)d_in[5];
    const float* bv     = (const float*)d_in[6];
    const float* wc     = (const float*)d_in[7];
    // d_in[8] = bc: softmax-invariant, unused.
    float* out = (float*)d_out;

    prep_qt_kernel<<<NB, NH>>>(query, Wq, bq, bv);
    prep_wfrag_kernel<<<256, 256>>>(Wv);
    scores_kernel<<<NROWS / 64, 512>>>(values, wc);
    softmax_kernel<<<NB, 1024>>>(mask, out);
    context_partial_kernel<<<NB * 8, 512>>>(values, out);
    context_reduce_kernel<<<NB, 512>>>(out);
}

// round 8
// speedup vs baseline: 1.6064x; 1.0089x over previous
#include <cuda_runtime.h>
#include <cuda_fp16.h>
#include <cstdint>

// Problem shape (fixed by the reference)
#define NB 32
#define NS 4096
#define NH 512
#define NROWS (NB * NS)   // 131072 rows of the fused [B*S, H] GEMM

// ---------------------------------------------------------------------------
// Device scratch (no cudaMalloc allowed)
// ---------------------------------------------------------------------------
__device__ float g_qt[NB * NH];                   // q@Wq + bq + bv, fp32
// B operand in FRAGMENT order: [nb(64)][kstep(32)][lane(32)] = {b0,b1} uint2.
// b0 = fp16(Wv[k0][n]),fp16(Wv[k0+1][n]); b1 = same at k0+8, with
// n = nb*8 + (lane>>2), k0 = kstep*16 + (lane&3)*2.  Warp fragment load is a
// single fully-coalesced 256B LDG.64 burst (lane l reads 8B at base+8l).
__device__ __align__(16) uint2 g_Wfrag[64 * 32 * 32];
__device__ float g_scores[NB * NS];               // pre-softmax scores
__device__ float g_partial[NB * 16 * NH];         // split-K context partials

// ---------------------------------------------------------------------------
// Helpers
// ---------------------------------------------------------------------------
__device__ __forceinline__ float tanh_fast(float x) {
    float y;
    asm("tanh.approx.f32 %0, %1;" : "=f"(y) : "f"(x));
    return y;
}

// m16n8k16 fp16 MMA, fp32 accumulate (sm_80+, valid on plain sm_100 target)
__device__ __forceinline__ void mma16816(float* d,
                                         uint32_t a0, uint32_t a1,
                                         uint32_t a2, uint32_t a3,
                                         uint32_t b0, uint32_t b1) {
    asm volatile(
        "mma.sync.aligned.m16n8k16.row.col.f32.f16.f16.f32 "
        "{%0,%1,%2,%3}, {%4,%5,%6,%7}, {%8,%9}, {%0,%1,%2,%3};"
        : "+f"(d[0]), "+f"(d[1]), "+f"(d[2]), "+f"(d[3])
        : "r"(a0), "r"(a1), "r"(a2), "r"(a3), "r"(b0), "r"(b1));
}

// ---------------------------------------------------------------------------
// Kernel 1: q_t[b][k] = bq[k] + bv[k] + sum_h query[b][h] * Wq[h][k]
// (bv folded in; bc dropped: constant per-row shift is softmax-invariant and
//  scores themselves are not part of the output.)
// ---------------------------------------------------------------------------
__global__ void prep_qt_kernel(const float* __restrict__ query,
                               const float* __restrict__ Wq,
                               const float* __restrict__ bq,
                               const float* __restrict__ bv) {
    __shared__ float qs[NH];
    int b = blockIdx.x;
    int k = threadIdx.x;
    qs[k] = query[b * NH + k];
    __syncthreads();
    float acc = bq[k] + bv[k];
#pragma unroll 8
    for (int h = 0; h < NH; h++)
        acc = fmaf(qs[h], Wq[h * NH + k], acc);
    g_qt[b * NH + k] = acc;
}

// ---------------------------------------------------------------------------
// Kernel 2: pack Wv -> fragment-ordered fp16 B operand g_Wfrag (512 KB).
// One thread per uint2.  Wv is 1 MB -> L2-resident; cost ~5 us.
// ---------------------------------------------------------------------------
__global__ void prep_wfrag_kernel(const float* __restrict__ Wv) {
    int i = blockIdx.x * blockDim.x + threadIdx.x;   // 65536 total
    int lane = i & 31;
    int ks = (i >> 5) & 31;
    int nb = i >> 10;
    int g = lane >> 2;
    int t = lane & 3;
    int n = nb * 8 + g;
    int k0 = ks * 16 + t * 2;

    __half2 b0 = __floats2half2_rn(Wv[(size_t)k0 * NH + n],
                                   Wv[(size_t)(k0 + 1) * NH + n]);
    __half2 b1 = __floats2half2_rn(Wv[(size_t)(k0 + 8) * NH + n],
                                   Wv[(size_t)(k0 + 9) * NH + n]);
    uint2 u;
    u.x = *(uint32_t*)&b0;
    u.y = *(uint32_t*)&b1;
    g_Wfrag[i] = u;
}

// ---------------------------------------------------------------------------
// Kernel 3: fused scores via HMMA mma.sync.
// Double-buffered A staging + fragment-ordered B with a 1-deep B software
// pipeline: next kstep's 4 coalesced LDG.64 are issued BEFORE the current
// kstep's 16 MMAs, and the pipeline runs straight across chunk boundaries
// (B loads are register-only, independent of the A smem barrier).
// CTA: 512 threads (16 warps), M = 64 rows, N = 512, K = 512 in 4 chunks.
// Epilogue: score[row] = sum_h wc[h]*tanh(qt[b][h] + v_t[row][h]) — the
// 256 MB v_t never touches memory.
// ---------------------------------------------------------------------------
#define AS_STRIDE 136   // halves per A smem row (136*2 = 272 B -> bank shift 4/row)

__global__ void __launch_bounds__(512) scores_kernel(const float* __restrict__ values,
                                                     const float* __restrict__ wc) {
    __shared__ __half As[2][64 * AS_STRIDE];   // 2 x 17408 B
    __shared__ float qt_s[NH];
    __shared__ float wc_s[NH];
    __shared__ float red[64 * 16];

    int tid = threadIdx.x;
    int w = tid >> 5;
    int l = tid & 31;
    int g = l >> 2;   // group id (0..7)
    int t = l & 3;    // thread-in-group
    int row_base = blockIdx.x * 64;
    int b = row_base >> 12;  // 4096 rows per batch, 64 | 4096

    for (int i = tid; i < NH; i += 512) {
        qt_s[i] = g_qt[b * NH + i];
        wc_s[i] = wc[i];
    }

    float acc[4][4][4];
#pragma unroll
    for (int mt = 0; mt < 4; mt++)
#pragma unroll
        for (int nt = 0; nt < 4; nt++)
#pragma unroll
            for (int j = 0; j < 4; j++)
                acc[mt][nt][j] = 0.f;

    // Fragment base for this warp+lane: nb = w*4 + nt, kstep = kc*8 + ks.
    const uint2* wf = g_Wfrag + ((size_t)(w * 4) * 32) * 32 + l;

    float4 pf[4];
    uint2 bfc[4], bfn[4];

    // ---- preload chunk 0 A and kstep 0 B ----
#pragma unroll
    for (int i = 0; i < 4; i++) {
        int r = i * 16 + w;
        pf[i] = *((const float4*)(values + (size_t)(row_base + r) * NH) + l);
    }
#pragma unroll
    for (int nt = 0; nt < 4; nt++)
        bfc[nt] = wf[(size_t)nt * 32 * 32];
#pragma unroll
    for (int i = 0; i < 4; i++) {
        int r = i * 16 + w;
        __half2 h0 = __floats2half2_rn(pf[i].x, pf[i].y);
        __half2 h1 = __floats2half2_rn(pf[i].z, pf[i].w);
        uint2 st;
        st.x = *(uint32_t*)&h0;
        st.y = *(uint32_t*)&h1;
        *(uint2*)(&As[0][r * AS_STRIDE + l * 4]) = st;
    }
    __syncthreads();

    for (int kc = 0; kc < 4; kc++) {
        int cur = kc & 1;

        // ---- issue next chunk's A LDGs (consumed only after the MMAs) ----
        if (kc < 3) {
#pragma unroll
            for (int i = 0; i < 4; i++) {
                int r = i * 16 + w;
                pf[i] = *((const float4*)(values + (size_t)(row_base + r) * NH +
                                          (kc + 1) * 128) + l);
            }
        }

        // ---- 8 k-steps of K=16 on As[cur], B pipelined 1 deep ----
#pragma unroll
        for (int ks = 0; ks < 8; ks++) {
            int kstep = kc * 8 + ks;
            // prefetch next kstep's B (crosses chunk boundary freely)
            if (!(kc == 3 && ks == 7)) {
#pragma unroll
                for (int nt = 0; nt < 4; nt++)
                    bfn[nt] = wf[((size_t)nt * 32 + kstep + 1) * 32];
            }
#pragma unroll
            for (int mt = 0; mt < 4; mt++) {
                const __half* ab = &As[cur][(mt * 16 + g) * AS_STRIDE + ks * 16 + t * 2];
                uint32_t a0 = *(const uint32_t*)ab;
                uint32_t a1 = *(const uint32_t*)(ab + 8 * AS_STRIDE);
                uint32_t a2 = *(const uint32_t*)(ab + 8);
                uint32_t a3 = *(const uint32_t*)(ab + 8 * AS_STRIDE + 8);
#pragma unroll
                for (int nt = 0; nt < 4; nt++)
                    mma16816(acc[mt][nt], a0, a1, a2, a3, bfc[nt].x, bfc[nt].y);
            }
#pragma unroll
            for (int nt = 0; nt < 4; nt++)
                bfc[nt] = bfn[nt];
        }

        // ---- convert + store prefetched A chunk into the other buffer ----
        if (kc < 3) {
#pragma unroll
            for (int i = 0; i < 4; i++) {
                int r = i * 16 + w;
                __half2 h0 = __floats2half2_rn(pf[i].x, pf[i].y);
                __half2 h1 = __floats2half2_rn(pf[i].z, pf[i].w);
                uint2 st;
                st.x = *(uint32_t*)&h0;
                st.y = *(uint32_t*)&h1;
                *(uint2*)(&As[cur ^ 1][r * AS_STRIDE + l * 4]) = st;
            }
        }
        __syncthreads();
    }

    // ---- epilogue: wc * tanh(qt + v_t), reduce over this warp's 32 cols ----
    float rs[8];
#pragma unroll
    for (int i = 0; i < 8; i++) rs[i] = 0.f;

#pragma unroll
    for (int nt = 0; nt < 4; nt++) {
        int c0 = w * 32 + nt * 8 + t * 2;
        float w0 = wc_s[c0], w1 = wc_s[c0 + 1];
        float q0 = qt_s[c0], q1 = qt_s[c0 + 1];
#pragma unroll
        for (int mt = 0; mt < 4; mt++) {
            float* d = acc[mt][nt];
            rs[mt * 2]     += w0 * tanh_fast(d[0] + q0) + w1 * tanh_fast(d[1] + q1);
            rs[mt * 2 + 1] += w0 * tanh_fast(d[2] + q0) + w1 * tanh_fast(d[3] + q1);
        }
    }
#pragma unroll
    for (int i = 0; i < 8; i++) {
        rs[i] += __shfl_xor_sync(0xffffffffu, rs[i], 1);
        rs[i] += __shfl_xor_sync(0xffffffffu, rs[i], 2);
    }
    if (t == 0) {
#pragma unroll
        for (int mt = 0; mt < 4; mt++) {
            red[(mt * 16 + g) * 16 + w]     = rs[mt * 2];
            red[(mt * 16 + g + 8) * 16 + w] = rs[mt * 2 + 1];
        }
    }
    __syncthreads();
    if (tid < 64) {
        float s = 0.f;
#pragma unroll
        for (int j = 0; j < 16; j++) s += red[tid * 16 + j];
        g_scores[row_base + tid] = s;
    }
}

// ---------------------------------------------------------------------------
// Kernel 4: softmax over S per batch, writes attn into d_out[B*H ..]
// ---------------------------------------------------------------------------
__global__ void softmax_kernel(const int* __restrict__ mask, float* __restrict__ out) {
    __shared__ float red[1024];
    int b = blockIdx.x;
    int tid = threadIdx.x;  // 1024 threads, 4 elems each

    float v[4];
#pragma unroll
    for (int i = 0; i < 4; i++) {
        int s = tid + i * 1024;
        float sc = g_scores[b * NS + s];
        v[i] = (mask[b * NS + s] == 0) ? -1e30f : sc;
    }
    float mx = fmaxf(fmaxf(v[0], v[1]), fmaxf(v[2], v[3]));
    red[tid] = mx;
    __syncthreads();
    for (int off = 512; off > 0; off >>= 1) {
        if (tid < off) red[tid] = fmaxf(red[tid], red[tid + off]);
        __syncthreads();
    }
    mx = red[0];
    __syncthreads();

    float e[4];
    float sm = 0.f;
#pragma unroll
    for (int i = 0; i < 4; i++) {
        e[i] = __expf(v[i] - mx);
        sm += e[i];
    }
    red[tid] = sm;
    __syncthreads();
    for (int off = 512; off > 0; off >>= 1) {
        if (tid < off) red[tid] += red[tid + off];
        __syncthreads();
    }
    float inv = 1.f / red[0];

    float* attn = out + NB * NH;
#pragma unroll
    for (int i = 0; i < 4; i++)
        attn[b * NS + tid + i * 1024] = e[i] * inv;
}

// ---------------------------------------------------------------------------
// Kernel 5: split-K context partials: block (b, sp) sums 256 s-rows for all H
// ---------------------------------------------------------------------------
__global__ void context_partial_kernel(const float* __restrict__ values,
                                       const float* __restrict__ out) {
    int bs = blockIdx.x;             // 0..511
    int b = bs >> 4;
    int sp = bs & 15;
    int h = threadIdx.x;             // 512
    const float* attn = out + NB * NH + b * NS + sp * 256;
    const float* vb = values + ((size_t)b * NS + (size_t)sp * 256) * NH;
    float acc = 0.f;
#pragma unroll 8
    for (int s = 0; s < 256; s++)
        acc = fmaf(attn[s], vb[(size_t)s * NH + h], acc);
    g_partial[bs * NH + h] = acc;
}

// ---------------------------------------------------------------------------
// Kernel 6: reduce partials -> context in d_out[0 .. B*H)
// ---------------------------------------------------------------------------
__global__ void context_reduce_kernel(float* __restrict__ out) {
    int b = blockIdx.x;
    int h = threadIdx.x;
    float acc = 0.f;
#pragma unroll
    for (int p = 0; p < 16; p++)
        acc += g_partial[(b * 16 + p) * NH + h];
    out[b * NH + h] = acc;
}

// ---------------------------------------------------------------------------
// Launch: out = [ context (B*H) | attn (B*S) ]  (tuple order of reference)
// ---------------------------------------------------------------------------
extern "C" void kernel_launch(void* const* d_in, const int* in_sizes, int n_in,
                              void* d_out, int out_size) {
    const float* query  = (const float*)d_in[0];
    const float* values = (const float*)d_in[1];
    const int*   mask   = (const int*)  d_in[2];
    const float* Wq     = (const float*)d_in[3];
    const float* bq     = (const float*)d_in[4];
    const float* Wv     = (const float*)d_in[5];
    const float* bv     = (const float*)d_in[6];
    const float* wc     = (const float*)d_in[7];
    // d_in[8] = bc: softmax-invariant, unused.
    float* out = (float*)d_out;

    prep_qt_kernel<<<NB, NH>>>(query, Wq, bq, bv);
    prep_wfrag_kernel<<<256, 256>>>(Wv);
    scores_kernel<<<NROWS / 64, 512>>>(values, wc);
    softmax_kernel<<<NB, 1024>>>(mask, out);
    context_partial_kernel<<<NB * 16, 512>>>(values, out);
    context_reduce_kernel<<<NB, 512>>>(out);
}